// round 8
// baseline (speedup 1.0000x reference)
#include <cuda_runtime.h>
#include <cuda_bf16.h>
#include <cstdint>
#include <cstddef>
#include <math.h>

// ---------------------------------------------------------------------------
// Problem dims (fixed by the dataset)
// ---------------------------------------------------------------------------
#define MDIM 16384          // B*S = 8*2048
#define NDIM 4096           // D_OUT
#define KDIM 4096           // D_IN
#define K2   8192           // hi+lo int8 planes (bytes per A row)

#define BM 128
#define BN 128
#define BKB 128             // K-bytes per stage (128 int8)
#define STAGES 4
#define NITER (K2 / BKB)    // 64 (0..31 = h plane, 32..63 = l plane)

// Stage layout: [A 16KB][B 16KB] per stage, 4 stages = 128KB dynamic smem
#define STAGE_BYTES 32768
#define SMEM_BYTES (STAGES * STAGE_BYTES)

// ---------------------------------------------------------------------------
// Device scratch (static globals: no allocation in kernel_launch)
// ---------------------------------------------------------------------------
__device__ int8_t g_Ai[(size_t)MDIM * K2];    // 128 MB: [m][0..4095]=h, [m][4096..8191]=l
__device__ int8_t g_Bi[(size_t)NDIM * KDIM];  // 16 MB: ternary weights {-1,0,1}
__device__ double g_partial[4096];
__device__ float  g_partf[4096];
__device__ float  g_gamma;
__device__ float  g_scale;                    // s = max|x| / 127

// NOTE: host is aarch64 (Grace) -> plain `char` is UNSIGNED. All quantized
// stores must go through signed conversion: float -> int -> int8_t.
__device__ __forceinline__ int8_t to_s8(float v) {
    return (int8_t)(int)v;
}

// ---------------------------------------------------------------------------
// PTX helpers (family-portable: cp.async / ldmatrix / mma.sync only)
// ---------------------------------------------------------------------------
__device__ __forceinline__ uint32_t s2u(const void* p) {
    return (uint32_t)__cvta_generic_to_shared(p);
}

__device__ __forceinline__ void cp_async16(uint32_t smem_dst, const void* gmem_src) {
    asm volatile("cp.async.cg.shared.global [%0], [%1], 16;"
                 :: "r"(smem_dst), "l"(gmem_src));
}
__device__ __forceinline__ void cp_commit() {
    asm volatile("cp.async.commit_group;");
}
__device__ __forceinline__ void cp_wait2() {
    asm volatile("cp.async.wait_group %0;" :: "n"(STAGES - 2));
}

__device__ __forceinline__ void ldmatrix_x4(uint32_t& r0, uint32_t& r1, uint32_t& r2,
                                            uint32_t& r3, uint32_t addr) {
    asm volatile("ldmatrix.sync.aligned.m8n8.x4.shared.b16 {%0,%1,%2,%3}, [%4];"
                 : "=r"(r0), "=r"(r1), "=r"(r2), "=r"(r3) : "r"(addr));
}

__device__ __forceinline__ void mma_s8(int& c0, int& c1, int& c2, int& c3,
                                       uint32_t a0, uint32_t a1, uint32_t a2, uint32_t a3,
                                       uint32_t b0, uint32_t b1) {
    asm volatile("mma.sync.aligned.m16n8k32.row.col.s32.s8.s8.s32 "
                 "{%0,%1,%2,%3}, {%4,%5,%6,%7}, {%8,%9}, {%0,%1,%2,%3};"
                 : "+r"(c0), "+r"(c1), "+r"(c2), "+r"(c3)
                 : "r"(a0), "r"(a1), "r"(a2), "r"(a3), "r"(b0), "r"(b1));
}

// ---------------------------------------------------------------------------
// Prep kernels
// ---------------------------------------------------------------------------
// gamma = mean|w|, deterministic two-stage double tree.
__global__ void k_reduce1(const float* __restrict__ w) {
    __shared__ double sdata[256];
    const float* p = w + (size_t)blockIdx.x * 4096;
    double s = 0.0;
    for (int i = threadIdx.x; i < 4096; i += 256) s += (double)fabsf(p[i]);
    sdata[threadIdx.x] = s;
    __syncthreads();
    for (int st = 128; st > 0; st >>= 1) {
        if (threadIdx.x < st) sdata[threadIdx.x] += sdata[threadIdx.x + st];
        __syncthreads();
    }
    if (threadIdx.x == 0) g_partial[blockIdx.x] = sdata[0];
}
__global__ void k_reduce2() {
    __shared__ double sdata[256];
    double s = 0.0;
    for (int i = threadIdx.x; i < 4096; i += 256) s += g_partial[i];
    sdata[threadIdx.x] = s;
    __syncthreads();
    for (int st = 128; st > 0; st >>= 1) {
        if (threadIdx.x < st) sdata[threadIdx.x] += sdata[threadIdx.x + st];
        __syncthreads();
    }
    if (threadIdx.x == 0) g_gamma = (float)(sdata[0] / 16777216.0);
}

// max|x| (deterministic: max is order-independent). Block = 16384 floats.
__global__ void k_max1(const float* __restrict__ x) {
    __shared__ float sdata[256];
    const float4* p = reinterpret_cast<const float4*>(x + (size_t)blockIdx.x * 16384);
    float mx = 0.0f;
    for (int i = threadIdx.x; i < 4096; i += 256) {
        float4 v = p[i];
        mx = fmaxf(mx, fmaxf(fmaxf(fabsf(v.x), fabsf(v.y)), fmaxf(fabsf(v.z), fabsf(v.w))));
    }
    sdata[threadIdx.x] = mx;
    __syncthreads();
    for (int st = 128; st > 0; st >>= 1) {
        if (threadIdx.x < st) sdata[threadIdx.x] = fmaxf(sdata[threadIdx.x], sdata[threadIdx.x + st]);
        __syncthreads();
    }
    if (threadIdx.x == 0) g_partf[blockIdx.x] = sdata[0];
}
__global__ void k_max2() {
    __shared__ float sdata[256];
    float mx = 0.0f;
    for (int i = threadIdx.x; i < 4096; i += 256) mx = fmaxf(mx, g_partf[i]);
    sdata[threadIdx.x] = mx;
    __syncthreads();
    for (int st = 128; st > 0; st >>= 1) {
        if (threadIdx.x < st) sdata[threadIdx.x] = fmaxf(sdata[threadIdx.x], sdata[threadIdx.x + st]);
        __syncthreads();
    }
    if (threadIdx.x == 0) g_scale = sdata[0] / 127.0f;
}

// Quantize weights to ternary int8 {-1,0,1}. Reference op order:
// clip(round(w / (gamma+eps) * half), -half, half) = half * t.
__global__ void k_quantw(const float* __restrict__ w, float halfv) {
    size_t i4 = (size_t)blockIdx.x * blockDim.x + threadIdx.x;   // float4 index, exact grid
    float gamma = g_gamma;
    float denom = gamma + 1e-8f;
    float4 v = reinterpret_cast<const float4*>(w)[i4];
    int8_t o[4];
    float q;
    q = rintf(v.x / denom * halfv); o[0] = to_s8(fminf(fmaxf(q, -1.0f), 1.0f));
    q = rintf(v.y / denom * halfv); o[1] = to_s8(fminf(fmaxf(q, -1.0f), 1.0f));
    q = rintf(v.z / denom * halfv); o[2] = to_s8(fminf(fmaxf(q, -1.0f), 1.0f));
    q = rintf(v.w / denom * halfv); o[3] = to_s8(fminf(fmaxf(q, -1.0f), 1.0f));
    reinterpret_cast<uint32_t*>(g_Bi)[i4] = *reinterpret_cast<uint32_t*>(o);
}

// Split x into int8 h/l planes: x = s*(h + l/128) + err, |err| <= s/256.
__global__ void k_convx(const float* __restrict__ x) {
    size_t i4 = (size_t)blockIdx.x * blockDim.x + threadIdx.x;   // float4 index, exact grid
    size_t i = i4 * 4;
    int m = (int)(i >> 12);
    int k = (int)(i & 4095);
    float inv = 1.0f / g_scale;
    float4 v = reinterpret_cast<const float4*>(x)[i4];
    float h0 = rintf(v.x * inv), h1 = rintf(v.y * inv), h2 = rintf(v.z * inv), h3 = rintf(v.w * inv);
    int8_t hc[4], lc4[4];
    hc[0] = to_s8(h0); lc4[0] = to_s8(rintf((v.x * inv - h0) * 128.0f));
    hc[1] = to_s8(h1); lc4[1] = to_s8(rintf((v.y * inv - h1) * 128.0f));
    hc[2] = to_s8(h2); lc4[2] = to_s8(rintf((v.z * inv - h2) * 128.0f));
    hc[3] = to_s8(h3); lc4[3] = to_s8(rintf((v.w * inv - h3) * 128.0f));
    *reinterpret_cast<uint32_t*>(g_Ai + (size_t)m * K2 + k) = *reinterpret_cast<uint32_t*>(hc);
    *reinterpret_cast<uint32_t*>(g_Ai + (size_t)m * K2 + 4096 + k) = *reinterpret_cast<uint32_t*>(lc4);
}

// ---------------------------------------------------------------------------
// Main GEMM: IMMA s8 m16n8k32, BM=128 x BN=128 x BKB=128, 4-stage cp.async
// 8 warps: 2 (m) x 4 (n); warp tile 64x32.
// Plane h (iters 0..31) -> fold to float; plane l (32..63) -> combine /128.
// out = (facc + iacc/128) * (s*half) + bias
// ---------------------------------------------------------------------------
__global__ void __launch_bounds__(256, 1) k_gemm(
    const float* __restrict__ bias,
    float* __restrict__ out,
    float halfv)
{
    extern __shared__ char smem[];
    const uint32_t sb = s2u(smem);
    const int tid = threadIdx.x;
    const int wid = tid >> 5;
    const int lane = tid & 31;
    const int wm = wid >> 2;         // 0..1
    const int wn = wid & 3;          // 0..3

    const int nt_blk = blockIdx.x & 31;      // nt fastest: B + A-row reuse in L2
    const int mt_blk = blockIdx.x >> 5;
    const int m0 = mt_blk * BM;
    const int n0 = nt_blk * BN;

    const int8_t* gA = g_Ai;
    const int8_t* gB = g_Bi;

    // --- per-thread cp.async mapping: 2 threads per row, 4x16B chunks each ---
    const int ldrow = tid >> 1;               // 0..127
    const int ldcb  = (tid & 1) * 4;          // chunk base 0 or 4
    const size_t a_row_off = (size_t)(m0 + ldrow) * K2;
    const size_t b_row_off = (size_t)(n0 + ldrow) * KDIM;
    const uint32_t a_smem_row = sb + ldrow * 128;
    const uint32_t b_smem_row = sb + 16384 + ldrow * 128;
    const int rsw = ldrow & 7;

    int   iacc[4][4][4];
    float facc[4][4][4];
    #pragma unroll
    for (int i = 0; i < 4; i++)
        #pragma unroll
        for (int j = 0; j < 4; j++)
            #pragma unroll
            for (int k = 0; k < 4; k++) iacc[i][j][k] = 0;

    // --- prologue: issue stages 0..STAGES-2 ---
    #pragma unroll
    for (int s = 0; s < STAGES - 1; s++) {
        const int kA = s * BKB;
        const int kB = (s & 31) * BKB;
        #pragma unroll
        for (int j = 0; j < 4; j++) {
            int c = ldcb + j;
            cp_async16(a_smem_row + s * STAGE_BYTES + ((c ^ rsw) << 4),
                       gA + a_row_off + kA + c * 16);
            cp_async16(b_smem_row + s * STAGE_BYTES + ((c ^ rsw) << 4),
                       gB + b_row_off + kB + c * 16);
        }
        cp_commit();
    }

    int smem_read = 0, smem_write = STAGES - 1;

    for (int it = 0; it < NITER; ++it) {
        cp_wait2();
        __syncthreads();

        // issue loads for it + STAGES - 1
        const int itn = it + STAGES - 1;
        if (itn < NITER) {
            const int kA = itn * BKB;
            const int kB = (itn & 31) * BKB;
            #pragma unroll
            for (int j = 0; j < 4; j++) {
                int c = ldcb + j;
                cp_async16(a_smem_row + smem_write * STAGE_BYTES + ((c ^ rsw) << 4),
                           gA + a_row_off + kA + c * 16);
                cp_async16(b_smem_row + smem_write * STAGE_BYTES + ((c ^ rsw) << 4),
                           gB + b_row_off + kB + c * 16);
            }
        }
        cp_commit();

        // --- compute current stage: 4 k-steps of k32 ---
        const uint32_t aBase = sb + smem_read * STAGE_BYTES;
        const uint32_t bBase = aBase + 16384;
        const int lr = lane & 15;
        const int lc = lane >> 4;

        #pragma unroll
        for (int ks = 0; ks < 4; ks++) {
            uint32_t a[4][4];
            uint32_t b[4][2];
            #pragma unroll
            for (int mt = 0; mt < 4; mt++) {
                int r = wm * 64 + mt * 16 + lr;
                int c = ks * 2 + lc;
                uint32_t ad = aBase + r * 128 + (((c ^ (r & 7))) << 4);
                ldmatrix_x4(a[mt][0], a[mt][1], a[mt][2], a[mt][3], ad);
            }
            #pragma unroll
            for (int nh = 0; nh < 2; nh++) {
                int r = wn * 32 + nh * 16 + lr;
                int c = ks * 2 + lc;
                uint32_t bd = bBase + r * 128 + (((c ^ (r & 7))) << 4);
                uint32_t t0, t1, t2, t3;
                ldmatrix_x4(t0, t1, t2, t3, bd);
                b[nh * 2 + 0][0] = t0; b[nh * 2 + 0][1] = t2;
                b[nh * 2 + 1][0] = t1; b[nh * 2 + 1][1] = t3;
            }
            #pragma unroll
            for (int mt = 0; mt < 4; mt++)
                #pragma unroll
                for (int nt = 0; nt < 4; nt++)
                    mma_s8(iacc[mt][nt][0], iacc[mt][nt][1], iacc[mt][nt][2], iacc[mt][nt][3],
                           a[mt][0], a[mt][1], a[mt][2], a[mt][3],
                           b[nt][0], b[nt][1]);
        }

        // plane-h -> float fold, reset int acc for plane-l
        if (it == NITER / 2 - 1) {
            #pragma unroll
            for (int mt = 0; mt < 4; mt++)
                #pragma unroll
                for (int nt = 0; nt < 4; nt++)
                    #pragma unroll
                    for (int k = 0; k < 4; k++) {
                        facc[mt][nt][k] = (float)iacc[mt][nt][k];
                        iacc[mt][nt][k] = 0;
                    }
        }

        smem_read = (smem_read + 1 == STAGES) ? 0 : smem_read + 1;
        smem_write = (smem_write + 1 == STAGES) ? 0 : smem_write + 1;
    }

    // --- epilogue: out = (facc + iacc/128) * (s*half) + bias ---
    const float sc = g_scale * halfv;
    const int mbase = m0 + wm * 64;
    const int nbase = n0 + wn * 32;
    const int lrow = lane >> 2;
    const int lcol = (lane & 3) * 2;

    #pragma unroll
    for (int nt = 0; nt < 4; nt++) {
        const int col = nbase + nt * 8 + lcol;
        const float bx = __ldg(&bias[col]);
        const float by = __ldg(&bias[col + 1]);
        #pragma unroll
        for (int mt = 0; mt < 4; mt++) {
            const int row0 = mbase + mt * 16 + lrow;
            float2 v0, v1;
            v0.x = (facc[mt][nt][0] + (float)iacc[mt][nt][0] * 0.0078125f) * sc + bx;
            v0.y = (facc[mt][nt][1] + (float)iacc[mt][nt][1] * 0.0078125f) * sc + by;
            v1.x = (facc[mt][nt][2] + (float)iacc[mt][nt][2] * 0.0078125f) * sc + bx;
            v1.y = (facc[mt][nt][3] + (float)iacc[mt][nt][3] * 0.0078125f) * sc + by;
            *reinterpret_cast<float2*>(out + (size_t)row0 * NDIM + col) = v0;
            *reinterpret_cast<float2*>(out + (size_t)(row0 + 8) * NDIM + col) = v1;
        }
    }
}

// ---------------------------------------------------------------------------
// Host launch
// ---------------------------------------------------------------------------
extern "C" void kernel_launch(void* const* d_in, const int* in_sizes, int n_in,
                              void* d_out, int out_size) {
    // Identify inputs by size: x=67108864, w=16777216, bias=4096
    const float* x = nullptr; const float* w = nullptr; const float* bias = nullptr;
    for (int i = 0; i < n_in; i++) {
        if (in_sizes[i] == MDIM * KDIM)      x = (const float*)d_in[i];
        else if (in_sizes[i] == NDIM * KDIM) w = (const float*)d_in[i];
        else if (in_sizes[i] == NDIM)        bias = (const float*)d_in[i];
    }
    float* out = (float*)d_out;

    const float halfv = (float)((pow(2.0, 1.58) - 1.0) * 0.5);

    // Prep: gamma + max|x| (deterministic), W -> ternary s8, X -> h/l s8 planes
    k_reduce1<<<4096, 256>>>(w);
    k_reduce2<<<1, 256>>>();
    k_max1<<<4096, 256>>>(x);
    k_max2<<<1, 256>>>();
    k_quantw<<<(NDIM * KDIM) / (256 * 4), 256>>>(w, halfv);
    k_convx<<<(MDIM * KDIM) / (256 * 4), 256>>>(x);

    // GEMM
    static bool attr_set = false;
    if (!attr_set) {
        cudaFuncSetAttribute(k_gemm, cudaFuncAttributeMaxDynamicSharedMemorySize, SMEM_BYTES);
        attr_set = true;
    }
    dim3 grid((MDIM / BM) * (NDIM / BN));   // 128 * 32 = 4096 CTAs
    k_gemm<<<grid, 256, SMEM_BYTES>>>(bias, out, halfv);
}

// round 9
// speedup vs baseline: 4.2297x; 4.2297x over previous
#include <cuda_runtime.h>
#include <cuda_fp16.h>
#include <cstdint>
#include <cstddef>
#include <math.h>

// ---------------------------------------------------------------------------
// Problem dims (fixed by the dataset)
// ---------------------------------------------------------------------------
#define MDIM 16384          // B*S = 8*2048
#define NDIM 4096           // D_OUT
#define KDIM 4096           // D_IN

#define BM 128
#define BN 128
#define BK 64               // fp16 elements per stage (128 bytes per row)
#define STAGES 3
#define NITER (KDIM / BK)   // 64

// Stage layout: [A 16KB][B 16KB] per stage, 3 stages = 96KB dynamic smem
#define STAGE_BYTES 32768
#define SMEM_BYTES (STAGES * STAGE_BYTES)

// ---------------------------------------------------------------------------
// Device scratch (static globals: no allocation in kernel_launch)
// ---------------------------------------------------------------------------
__device__ __half g_A[(size_t)MDIM * KDIM];   // 128 MB: x as fp16 (single plane)
__device__ __half g_B[(size_t)NDIM * KDIM];   // 32 MB: ternary weights {-1,0,1}
__device__ double g_partial[4096];
__device__ float  g_gamma;

// ---------------------------------------------------------------------------
// PTX helpers (family-portable: cp.async / ldmatrix / mma.sync only)
// ---------------------------------------------------------------------------
__device__ __forceinline__ uint32_t s2u(const void* p) {
    return (uint32_t)__cvta_generic_to_shared(p);
}

__device__ __forceinline__ void cp_async16(uint32_t smem_dst, const void* gmem_src) {
    asm volatile("cp.async.cg.shared.global [%0], [%1], 16;"
                 :: "r"(smem_dst), "l"(gmem_src));
}
__device__ __forceinline__ void cp_commit() {
    asm volatile("cp.async.commit_group;");
}
__device__ __forceinline__ void cp_wait1() {
    asm volatile("cp.async.wait_group 1;");
}

__device__ __forceinline__ void ldmatrix_x4(uint32_t& r0, uint32_t& r1, uint32_t& r2,
                                            uint32_t& r3, uint32_t addr) {
    asm volatile("ldmatrix.sync.aligned.m8n8.x4.shared.b16 {%0,%1,%2,%3}, [%4];"
                 : "=r"(r0), "=r"(r1), "=r"(r2), "=r"(r3) : "r"(addr));
}

__device__ __forceinline__ void mma_f16(float& c0, float& c1, float& c2, float& c3,
                                        uint32_t a0, uint32_t a1, uint32_t a2, uint32_t a3,
                                        uint32_t b0, uint32_t b1) {
    asm volatile("mma.sync.aligned.m16n8k16.row.col.f32.f16.f16.f32 "
                 "{%0,%1,%2,%3}, {%4,%5,%6,%7}, {%8,%9}, {%0,%1,%2,%3};"
                 : "+f"(c0), "+f"(c1), "+f"(c2), "+f"(c3)
                 : "r"(a0), "r"(a1), "r"(a2), "r"(a3), "r"(b0), "r"(b1));
}

// ---------------------------------------------------------------------------
// Prep kernels
// ---------------------------------------------------------------------------
// gamma = mean|w|, deterministic two-stage double tree.
__global__ void k_reduce1(const float* __restrict__ w) {
    __shared__ double sdata[256];
    const float* p = w + (size_t)blockIdx.x * 4096;
    double s = 0.0;
    for (int i = threadIdx.x; i < 4096; i += 256) s += (double)fabsf(p[i]);
    sdata[threadIdx.x] = s;
    __syncthreads();
    for (int st = 128; st > 0; st >>= 1) {
        if (threadIdx.x < st) sdata[threadIdx.x] += sdata[threadIdx.x + st];
        __syncthreads();
    }
    if (threadIdx.x == 0) g_partial[blockIdx.x] = sdata[0];
}
__global__ void k_reduce2() {
    __shared__ double sdata[256];
    double s = 0.0;
    for (int i = threadIdx.x; i < 4096; i += 256) s += g_partial[i];
    sdata[threadIdx.x] = s;
    __syncthreads();
    for (int st = 128; st > 0; st >>= 1) {
        if (threadIdx.x < st) sdata[threadIdx.x] += sdata[threadIdx.x + st];
        __syncthreads();
    }
    if (threadIdx.x == 0) g_gamma = (float)(sdata[0] / 16777216.0);
}

// Quantize weights to ternary fp16 {-1,0,1} (the *h scale applied in epilogue).
// Exact reference op order: clip(round(w / (gamma+eps) * half), -half, half) = half*t.
__global__ void k_quantw(const float* __restrict__ w, float halfv) {
    size_t i4 = (size_t)blockIdx.x * blockDim.x + threadIdx.x;   // float4 index, exact grid
    float gamma = g_gamma;
    float denom = gamma + 1e-8f;
    float4 v = reinterpret_cast<const float4*>(w)[i4];
    __half o[4];
    float q;
    q = rintf(v.x / denom * halfv); o[0] = __float2half(fminf(fmaxf(q, -1.0f), 1.0f));
    q = rintf(v.y / denom * halfv); o[1] = __float2half(fminf(fmaxf(q, -1.0f), 1.0f));
    q = rintf(v.z / denom * halfv); o[2] = __float2half(fminf(fmaxf(q, -1.0f), 1.0f));
    q = rintf(v.w / denom * halfv); o[3] = __float2half(fminf(fmaxf(q, -1.0f), 1.0f));
    reinterpret_cast<uint64_t*>(g_B)[i4] = *reinterpret_cast<uint64_t*>(o);
}

// Convert x (fp32) -> fp16 plane.
__global__ void k_convx(const float* __restrict__ x) {
    size_t i4 = (size_t)blockIdx.x * blockDim.x + threadIdx.x;   // float4 index, exact grid
    float4 v = reinterpret_cast<const float4*>(x)[i4];
    __half o[4];
    o[0] = __float2half(v.x);
    o[1] = __float2half(v.y);
    o[2] = __float2half(v.z);
    o[3] = __float2half(v.w);
    reinterpret_cast<uint64_t*>(g_A)[i4] = *reinterpret_cast<uint64_t*>(o);
}

// ---------------------------------------------------------------------------
// Main GEMM: mma.sync fp16, BM=128 x BN=128 x BK=64, cp.async 3-stage pipeline
// 8 warps: 2 (m) x 4 (n); warp tile 64x32; out = acc*half + bias
// ---------------------------------------------------------------------------
__global__ void __launch_bounds__(256, 2) k_gemm(
    const float* __restrict__ bias,
    float* __restrict__ out,
    float halfv)
{
    extern __shared__ char smem[];
    const uint32_t sb = s2u(smem);
    const int tid = threadIdx.x;
    const int wid = tid >> 5;
    const int lane = tid & 31;
    const int wm = wid >> 2;         // 0..1
    const int wn = wid & 3;          // 0..3

    const int nt_blk = blockIdx.x & 31;      // nt fastest: B tile reuse in L2
    const int mt_blk = blockIdx.x >> 5;
    const int m0 = mt_blk * BM;
    const int n0 = nt_blk * BN;

    const __half* gA = g_A;
    const __half* gB = g_B;

    // --- per-thread cp.async mapping: 2 threads per row, 4x16B chunks each ---
    const int ldrow = tid >> 1;               // 0..127
    const int ldcb  = (tid & 1) * 4;          // chunk base 0 or 4
    const size_t a_row_off = (size_t)(m0 + ldrow) * KDIM;
    const size_t b_row_off = (size_t)(n0 + ldrow) * KDIM;
    const uint32_t a_smem_row = sb + ldrow * 128;
    const uint32_t b_smem_row = sb + 16384 + ldrow * 128;
    const int rsw = ldrow & 7;

    float acc[4][4][4];
    #pragma unroll
    for (int i = 0; i < 4; i++)
        #pragma unroll
        for (int j = 0; j < 4; j++)
            #pragma unroll
            for (int k = 0; k < 4; k++) acc[i][j][k] = 0.0f;

    // --- prologue: issue stages 0..STAGES-2 ---
    #pragma unroll
    for (int s = 0; s < STAGES - 1; s++) {
        const int kk = s * BK;
        #pragma unroll
        for (int j = 0; j < 4; j++) {
            int c = ldcb + j;
            cp_async16(a_smem_row + s * STAGE_BYTES + ((c ^ rsw) << 4),
                       gA + a_row_off + kk + c * 8);
            cp_async16(b_smem_row + s * STAGE_BYTES + ((c ^ rsw) << 4),
                       gB + b_row_off + kk + c * 8);
        }
        cp_commit();
    }

    int smem_read = 0, smem_write = STAGES - 1;

    for (int it = 0; it < NITER; ++it) {
        cp_wait1();
        __syncthreads();

        // issue loads for it + STAGES - 1
        const int itn = it + STAGES - 1;
        if (itn < NITER) {
            const int kk = itn * BK;
            #pragma unroll
            for (int j = 0; j < 4; j++) {
                int c = ldcb + j;
                cp_async16(a_smem_row + smem_write * STAGE_BYTES + ((c ^ rsw) << 4),
                           gA + a_row_off + kk + c * 8);
                cp_async16(b_smem_row + smem_write * STAGE_BYTES + ((c ^ rsw) << 4),
                           gB + b_row_off + kk + c * 8);
            }
        }
        cp_commit();

        // --- compute current stage: 4 k-steps of k16 ---
        const uint32_t aBase = sb + smem_read * STAGE_BYTES;
        const uint32_t bBase = aBase + 16384;
        const int lr = lane & 15;
        const int lc = lane >> 4;

        #pragma unroll
        for (int ks = 0; ks < 4; ks++) {
            uint32_t a[4][4];
            uint32_t b[4][2];
            #pragma unroll
            for (int mt = 0; mt < 4; mt++) {
                int r = wm * 64 + mt * 16 + lr;
                int c = ks * 2 + lc;
                uint32_t ad = aBase + r * 128 + (((c ^ (r & 7))) << 4);
                ldmatrix_x4(a[mt][0], a[mt][1], a[mt][2], a[mt][3], ad);
            }
            #pragma unroll
            for (int nh = 0; nh < 2; nh++) {
                int r = wn * 32 + nh * 16 + lr;
                int c = ks * 2 + lc;
                uint32_t bd = bBase + r * 128 + (((c ^ (r & 7))) << 4);
                uint32_t t0, t1, t2, t3;
                ldmatrix_x4(t0, t1, t2, t3, bd);
                b[nh * 2 + 0][0] = t0; b[nh * 2 + 0][1] = t2;
                b[nh * 2 + 1][0] = t1; b[nh * 2 + 1][1] = t3;
            }
            #pragma unroll
            for (int mt = 0; mt < 4; mt++)
                #pragma unroll
                for (int nt = 0; nt < 4; nt++)
                    mma_f16(acc[mt][nt][0], acc[mt][nt][1], acc[mt][nt][2], acc[mt][nt][3],
                            a[mt][0], a[mt][1], a[mt][2], a[mt][3],
                            b[nt][0], b[nt][1]);
        }

        smem_read = (smem_read + 1 == STAGES) ? 0 : smem_read + 1;
        smem_write = (smem_write + 1 == STAGES) ? 0 : smem_write + 1;
    }

    // --- epilogue: out = acc*half + bias ---
    const int mbase = m0 + wm * 64;
    const int nbase = n0 + wn * 32;
    const int lrow = lane >> 2;
    const int lcol = (lane & 3) * 2;

    #pragma unroll
    for (int nt = 0; nt < 4; nt++) {
        const int col = nbase + nt * 8 + lcol;
        const float bx = __ldg(&bias[col]);
        const float by = __ldg(&bias[col + 1]);
        #pragma unroll
        for (int mt = 0; mt < 4; mt++) {
            const int row0 = mbase + mt * 16 + lrow;
            float2 v0, v1;
            v0.x = acc[mt][nt][0] * halfv + bx;
            v0.y = acc[mt][nt][1] * halfv + by;
            v1.x = acc[mt][nt][2] * halfv + bx;
            v1.y = acc[mt][nt][3] * halfv + by;
            *reinterpret_cast<float2*>(out + (size_t)row0 * NDIM + col) = v0;
            *reinterpret_cast<float2*>(out + (size_t)(row0 + 8) * NDIM + col) = v1;
        }
    }
}

// ---------------------------------------------------------------------------
// Host launch
// ---------------------------------------------------------------------------
extern "C" void kernel_launch(void* const* d_in, const int* in_sizes, int n_in,
                              void* d_out, int out_size) {
    // Identify inputs by size: x=67108864, w=16777216, bias=4096
    const float* x = nullptr; const float* w = nullptr; const float* bias = nullptr;
    for (int i = 0; i < n_in; i++) {
        if (in_sizes[i] == MDIM * KDIM)      x = (const float*)d_in[i];
        else if (in_sizes[i] == NDIM * KDIM) w = (const float*)d_in[i];
        else if (in_sizes[i] == NDIM)        bias = (const float*)d_in[i];
    }
    float* out = (float*)d_out;

    const float halfv = (float)((pow(2.0, 1.58) - 1.0) * 0.5);

    // Prep: gamma (deterministic), W -> ternary fp16, X -> fp16
    k_reduce1<<<4096, 256>>>(w);
    k_reduce2<<<1, 256>>>();
    k_quantw<<<(NDIM * KDIM) / (256 * 4), 256>>>(w, halfv);
    k_convx<<<(MDIM * KDIM) / (256 * 4), 256>>>(x);

    // GEMM
    static bool attr_set = false;
    if (!attr_set) {
        cudaFuncSetAttribute(k_gemm, cudaFuncAttributeMaxDynamicSharedMemorySize, SMEM_BYTES);
        attr_set = true;
    }
    dim3 grid((MDIM / BM) * (NDIM / BN));   // 128 * 32 = 4096 CTAs
    k_gemm<<<grid, 256, SMEM_BYTES>>>(bias, out, halfv);
}